// round 2
// baseline (speedup 1.0000x reference)
#include <cuda_runtime.h>

#define TT 8192
#define BB 20
#define CCH 395
#define HH 10
#define GIN 800
#define KTOT 790
#define KPAD 792
#define BT 256
#define CK 8
#define NCHUNK 99
#define NLOG2E (-1.4426950408889634f)

typedef unsigned long long ull;

// scratch (device-global: no allocation allowed)
__device__ ull d_wpack[KPAD * 40];                 // pre-splatted, scale-folded gate weights
__device__ float d_pre[(size_t)BB * TT * HH * 4];  // pre-activations, layout [b][t][o][g]

__device__ __forceinline__ ull fma2(ull a, ull b, ull c) {
    ull d;
    asm("fma.rn.f32x2 %0, %1, %2, %3;" : "=l"(d) : "l"(a), "l"(b), "l"(c));
    return d;
}
__device__ __forceinline__ ull pack2(float lo, float hi) {
    ull d;
    asm("mov.b64 %0, {%1, %2};" : "=l"(d) : "f"(lo), "f"(hi));
    return d;
}
__device__ __forceinline__ ull splat2(float v) {
    ull d;
    asm("mov.b64 %0, {%1, %1};" : "=l"(d) : "f"(v));
    return d;
}
__device__ __forceinline__ void unpack2(ull v, float& lo, float& hi) {
    asm("mov.b64 {%0, %1}, %2;" : "=f"(lo), "=f"(hi) : "l"(v));
}
__device__ __forceinline__ float ex2f(float x) {
    float r;
    asm("ex2.approx.f32 %0, %1;" : "=f"(r) : "f"(x));
    return r;
}
__device__ __forceinline__ float rcpf(float x) {
    float r;
    asm("rcp.approx.f32 %0, %1;" : "=f"(r) : "f"(x));
    return r;
}

// ---------------------------------------------------------------------------
// Repack gate weights: d_wpack[k][g*10+h] = splat( scale_g * W_g[h][col(k)] )
// k < 395 -> x-part (col k) ; k >= 395 -> y-part (col k+10). Wh (cols 395..404)
// is handled in the scan kernel directly. scale folds -log2(e) (x2 for tanh
// gate u) so the scan's sigmoid/tanh need no pre-multiplies.
// ---------------------------------------------------------------------------
__global__ void repack_kernel(const float* __restrict__ Wf, const float* __restrict__ Wi,
                              const float* __restrict__ Wu, const float* __restrict__ Wo) {
    int idx = blockIdx.x * blockDim.x + threadIdx.x;
    if (idx >= KPAD * 40) return;
    int k = idx / 40;
    int gh = idx - k * 40;
    int g = gh / 10;
    int h = gh - g * 10;
    float w = 0.f;
    if (k < KTOT) {
        int col = (k < CCH) ? k : (k + 10);
        const float* W = (g == 0) ? Wf : (g == 1) ? Wi : (g == 2) ? Wu : Wo;
        float sc = (g == 2) ? 2.f * NLOG2E : NLOG2E;
        w = W[h * GIN + col] * sc;
    }
    d_wpack[idx] = splat2(w);
}

// ---------------------------------------------------------------------------
// Pre-activation GEMM: pre[b][t][o][g] = sum_k in[k][t] * W[k][g*10+o] + bias
// Block = (t-tile of 256, one b). Thread = 4 t (2 f32x2 pairs) x 10 outputs of
// one gate g. K staged in chunks of 8 rows through smem with register
// double-buffering (one LDG pipeline stage).
// ---------------------------------------------------------------------------
__global__ __launch_bounds__(256) void gemm_kernel(
    const float* __restrict__ x, const float* __restrict__ y,
    const float* __restrict__ bf, const float* __restrict__ bi,
    const float* __restrict__ bu, const float* __restrict__ bo) {
    __shared__ __align__(16) float s_in[CK][BT];
    __shared__ __align__(16) ull s_w[CK][40];

    int b = blockIdx.y;
    int t0 = blockIdx.x * BT;
    int tid = threadIdx.x;
    int r = tid >> 5, lane = tid & 31;   // staging role
    int tcol = tid & 63, g = tid >> 6;   // compute role

    ull acc0[10], acc1[10];
#pragma unroll
    for (int j = 0; j < 10; j++) { acc0[j] = 0ull; acc1[j] = 0ull; }

    float4 v0 = make_float4(0, 0, 0, 0), v1 = v0;
    float m1 = 0.f;
    int mode = 2;
    ull wr0 = 0, wr1 = 0;

    // prefetch chunk 0
    {
        int k = r;
        if (k < KTOT) {
            if (k < CCH) {
                const float* src = x + ((size_t)(b * CCH + k)) * TT + t0 + lane * 8;
                v0 = *(const float4*)src;
                v1 = *(const float4*)(src + 4);
                mode = 0;
            } else {
                const float* src = y + ((size_t)(b * CCH + (k - CCH))) * TT + t0 + lane * 8;
                v0 = *(const float4*)src;
                v1 = *(const float4*)(src + 4);
                mode = 1;
                if (lane == 0) m1 = (t0 > 0) ? src[-1] : 0.f;
            }
        } else {
            mode = 2;
        }
        const ull* wsrc = d_wpack;
        wr0 = wsrc[tid];
        if (tid < 64) wr1 = wsrc[tid + 256];
    }

    for (int chunk = 0; chunk < NCHUNK; ++chunk) {
        __syncthreads();  // previous compute done reading smem
        // commit current chunk to smem
        if (mode == 0) {
            *(float4*)&s_in[r][lane * 8] = v0;
            *(float4*)&s_in[r][lane * 8 + 4] = v1;
        } else if (mode == 1) {
            // y_prev: shift right by one t
            float vv[8] = {v0.x, v0.y, v0.z, v0.w, v1.x, v1.y, v1.z, v1.w};
#pragma unroll
            for (int jj = 0; jj < 8; jj++) {
                int col = lane * 8 + jj + 1;
                if (col < BT) s_in[r][col] = vv[jj];
            }
            if (lane == 0) s_in[r][0] = m1;
        } else {
            float4 z = make_float4(0, 0, 0, 0);
            *(float4*)&s_in[r][lane * 8] = z;
            *(float4*)&s_in[r][lane * 8 + 4] = z;
        }
        ((ull*)s_w)[tid] = wr0;
        if (tid < 64) ((ull*)s_w)[tid + 256] = wr1;

        // prefetch next chunk
        if (chunk + 1 < NCHUNK) {
            int k = (chunk + 1) * CK + r;
            if (k < KTOT) {
                if (k < CCH) {
                    const float* src = x + ((size_t)(b * CCH + k)) * TT + t0 + lane * 8;
                    v0 = *(const float4*)src;
                    v1 = *(const float4*)(src + 4);
                    mode = 0;
                } else {
                    const float* src = y + ((size_t)(b * CCH + (k - CCH))) * TT + t0 + lane * 8;
                    v0 = *(const float4*)src;
                    v1 = *(const float4*)(src + 4);
                    mode = 1;
                    if (lane == 0) m1 = (t0 > 0) ? src[-1] : 0.f;
                }
            } else {
                mode = 2;
            }
            const ull* wsrc = d_wpack + (size_t)(chunk + 1) * CK * 40;
            wr0 = wsrc[tid];
            if (tid < 64) wr1 = wsrc[tid + 256];
        }
        __syncthreads();  // smem visible

        // compute: 8 K-rows x (2 t-pairs x 10 outputs) fma2
#pragma unroll
        for (int cc = 0; cc < CK; cc++) {
            ull xv0 = *(const ull*)&s_in[cc][tcol * 4];
            ull xv1 = *(const ull*)&s_in[cc][tcol * 4 + 2];
            const ull* wrow = &s_w[cc][g * 10];
#pragma unroll
            for (int j = 0; j < 10; j++) {
                ull w = wrow[j];
                acc0[j] = fma2(xv0, w, acc0[j]);
                acc1[j] = fma2(xv1, w, acc1[j]);
            }
        }
    }

    // epilogue: add scaled bias, write pre[b][t][o][g]
    const float* bsrc = (g == 0) ? bf : (g == 1) ? bi : (g == 2) ? bu : bo;
    float sc = (g == 2) ? 2.f * NLOG2E : NLOG2E;
    int tb = t0 + tcol * 4;
#pragma unroll
    for (int j = 0; j < 10; j++) {
        float z0, z1, z2, z3;
        unpack2(acc0[j], z0, z1);
        unpack2(acc1[j], z2, z3);
        float bb = bsrc[j] * sc;
        size_t base = ((size_t)(b * TT + tb) * 10 + j) * 4 + g;
        d_pre[base] = z0 + bb;
        d_pre[base + 40] = z1 + bb;
        d_pre[base + 80] = z2 + bb;
        d_pre[base + 120] = z3 + bb;
    }
}

// ---------------------------------------------------------------------------
// Sequential scan: 1 warp per batch, lane = hidden unit. h broadcast by shfl,
// two packed f32x2 dot chains (f,i) and (u,o). Gates via exact EX2+RCP
// (weights/pre already scaled by -log2 e). Stores buffered 4 steps -> STG.128.
// ---------------------------------------------------------------------------
__global__ __launch_bounds__(32) void scan_kernel(
    const float* __restrict__ Wf, const float* __restrict__ Wi,
    const float* __restrict__ Wu, const float* __restrict__ Wo,
    const float* __restrict__ b_init, float* __restrict__ out) {
    int b = blockIdx.x;
    int lane = threadIdx.x;
    int o = lane < 10 ? lane : 9;

    ull wfi[10], wuo[10];
#pragma unroll
    for (int h = 0; h < 10; h++) {
        int col = o * GIN + CCH + h;
        wfi[h] = pack2(Wf[col] * NLOG2E, Wi[col] * NLOG2E);
        wuo[h] = pack2(Wu[col] * 2.f * NLOG2E, Wo[col] * NLOG2E);
    }
    float c = b_init[o];
    float hv = 0.f;

    const float4* prep = (const float4*)d_pre + (size_t)b * TT * 10 + o;
    float4 pf0 = prep[0];
    float4 pf1 = prep[10];
    float* outh = out + ((size_t)b * HH + o) * TT;

    auto step = [&](int t) -> float {
        float4 cur = pf0;
        pf0 = pf1;
        if (t + 2 < TT) pf1 = prep[(size_t)(t + 2) * 10];
        ull zfi = pack2(cur.x, cur.y);
        ull zuo = pack2(cur.z, cur.w);
#pragma unroll
        for (int j = 0; j < 10; j++) {
            float hj = __shfl_sync(0xffffffffu, hv, j);
            ull hh = splat2(hj);
            zfi = fma2(hh, wfi[j], zfi);
            zuo = fma2(hh, wuo[j], zuo);
        }
        float zf, zi, zu, zo;
        unpack2(zfi, zf, zi);
        unpack2(zuo, zu, zo);
        // z already scaled by -log2e (u by -2log2e): exact sigmoid/tanh
        float f = rcpf(1.f + ex2f(zf));
        float ig = rcpf(1.f + ex2f(zi));
        float u = __fmaf_rn(2.f, rcpf(1.f + ex2f(zu)), -1.f);
        float og = rcpf(1.f + ex2f(zo));
        c = __fmaf_rn(f, c, ig * u);
        float e = ex2f(2.f * NLOG2E * c);           // e^{-2c}
        float th = __fmaf_rn(2.f, rcpf(1.f + e), -1.f);
        hv = og * th;
        return hv;
    };

    for (int t = 0; t < TT; t += 4) {
        float4 hb;
        hb.x = step(t);
        hb.y = step(t + 1);
        hb.z = step(t + 2);
        hb.w = step(t + 3);
        if (lane < 10) *(float4*)(outh + t) = hb;
    }
    if (lane < 10) out[(size_t)BB * HH * TT + b * HH + lane] = c;
}

extern "C" void kernel_launch(void* const* d_in, const int* in_sizes, int n_in,
                              void* d_out, int out_size) {
    const float* x = (const float*)d_in[0];
    const float* y = (const float*)d_in[1];
    const float* Wf = (const float*)d_in[2];
    const float* bf = (const float*)d_in[3];
    const float* Wi = (const float*)d_in[4];
    const float* bi = (const float*)d_in[5];
    const float* Wu = (const float*)d_in[6];
    const float* bu = (const float*)d_in[7];
    const float* Wo = (const float*)d_in[8];
    const float* bo = (const float*)d_in[9];
    const float* b_init = (const float*)d_in[11];
    float* out = (float*)d_out;

    repack_kernel<<<(KPAD * 40 + 255) / 256, 256>>>(Wf, Wi, Wu, Wo);
    gemm_kernel<<<dim3(TT / BT, BB), 256>>>(x, y, bf, bi, bu, bo);
    scan_kernel<<<BB, 32>>>(Wf, Wi, Wu, Wo, b_init, out);
}